// round 3
// baseline (speedup 1.0000x reference)
#include <cuda_runtime.h>
#include <cstdint>

#define NITEMS  4096
#define TPB     512
#define NWARP   16
#define NIT     40
#define CAP     600.0f
#define TWO_CAP 1200.0f
#define DAMP    1e-3f

typedef unsigned long long u64p;   // packed f32x2

__device__ __forceinline__ float frcp(float v) {
    float r;
    asm("rcp.approx.ftz.f32 %0, %1;" : "=f"(r) : "f"(v));
    return r;
}
__device__ __forceinline__ u64p pack2(float lo, float hi) {
    u64p r;
    asm("mov.b64 %0, {%1, %2};" : "=l"(r) : "f"(lo), "f"(hi));
    return r;
}
__device__ __forceinline__ void unpack2(u64p v, float& lo, float& hi) {
    asm("mov.b64 {%0, %1}, %2;" : "=f"(lo), "=f"(hi) : "l"(v));
}
__device__ __forceinline__ u64p mul2(u64p a, u64p b) {
    u64p r;
    asm("mul.rn.f32x2 %0, %1, %2;" : "=l"(r) : "l"(a), "l"(b));
    return r;
}
__device__ __forceinline__ u64p fma2(u64p a, u64p b, u64p c) {
    u64p r;
    asm("fma.rn.f32x2 %0, %1, %2, %3;" : "=l"(r) : "l"(a), "l"(b), "l"(c));
    return r;
}

__device__ __forceinline__ float wsum32(float v) {
#pragma unroll
    for (int o = 16; o > 0; o >>= 1) v += __shfl_xor_sync(0xffffffffu, v, o);
    return v;
}
__device__ __forceinline__ float wmax32(float v) {
#pragma unroll
    for (int o = 16; o > 0; o >>= 1) v = fmaxf(v, __shfl_xor_sync(0xffffffffu, v, o));
    return v;
}
// reduce 16 per-warp partials (idx = lane&15), all lanes get the result
__device__ __forceinline__ float bsum16(float v) {
#pragma unroll
    for (int o = 8; o > 0; o >>= 1) v += __shfl_xor_sync(0xffffffffu, v, o);
    return v;
}
__device__ __forceinline__ float bmax16(float v) {
#pragma unroll
    for (int o = 8; o > 0; o >>= 1) v = fmaxf(v, __shfl_xor_sync(0xffffffffu, v, o));
    return v;
}

__global__ void __launch_bounds__(TPB, 2)
ipm_kernel(const float* __restrict__ costs,
           const float* __restrict__ wglob,
           float* __restrict__ out)
{
    __shared__ float sA[NWARP], sB[NWARP], sC[NWARP], sD[NWARP];

    const int tid = threadIdx.x, lane = tid & 31, wid = tid >> 5;

    // ---- load row into registers (packed), c negated -----------------------
    u64p cP[4], wP[4];
    float wsum = 0.0f;
    {
        const float4* cg = (const float4*)(costs + (size_t)blockIdx.x * NITEMS);
        const float4* wg = (const float4*)wglob;
#pragma unroll
        for (int h = 0; h < 2; h++) {
            const float4 cf = cg[h * TPB + tid];
            const float4 wf = wg[h * TPB + tid];
            cP[h * 2]     = pack2(-cf.x, -cf.y);
            cP[h * 2 + 1] = pack2(-cf.z, -cf.w);
            wP[h * 2]     = pack2(wf.x, wf.y);
            wP[h * 2 + 1] = pack2(wf.z, wf.w);
            wsum += (wf.x + wf.y) + (wf.z + wf.w);
        }
    }
    wsum = wsum32(wsum);
    if (lane == 0) sA[wid] = wsum;
    __syncthreads();
    wsum = bsum16(sA[lane & 15]);
    __syncthreads();                 // protect sA reuse in iteration 0

    const float x0 = CAP * frcp(wsum);   // equality-feasible interior start

    u64p xP[4], qS[4], iHS[4];
#pragma unroll
    for (int i = 0; i < 4; i++) xP[i] = pack2(x0, x0);

    const u64p one2  = pack2(1.0f, 1.0f);
    const u64p none2 = pack2(-1.0f, -1.0f);
    const u64p n22   = pack2(-2.0f, -2.0f);

    float lam = 0.0f, mupow = 1.0f;

#pragma unroll 1
    for (int it = 0; it < NIT; ++it) {
        const float muc = fmaxf(mupow, DAMP);
        mupow *= 0.25f;              // aggressive path: mu quarters each step
        const u64p tmu2 = pack2(2.0f * muc, 2.0f * muc);
        const u64p nmu2 = pack2(-muc, -muc);
        const u64p lam2 = pack2(lam, lam);

        // ---- Pass A: q = 1/(x(1-x)), iH = mu/H, KKT residual sums ----------
        // one rcp/elem: p=x(1-x), s=1-2p, r=1/(p^2 s) => 1/p = r p s, mu/H = r p^4
        float s1 = 0.f, s2 = 0.f, s3 = 0.f;
        {
            u64p a1 = 0ull, a2 = 0ull, a3 = 0ull;
#pragma unroll
            for (int idx = 0; idx < 4; idx++) {
                const u64p xv  = xP[idx];
                const u64p wv  = wP[idx];
                const u64p omx = fma2(xv, none2, one2);     // 1-x
                const u64p p   = mul2(xv, omx);
                const u64p s   = fma2(p, n22, one2);        // 1-2p
                const u64p p2  = mul2(p, p);
                const u64p arg = mul2(p2, s);
                float g0, g1; unpack2(arg, g0, g1);
                const u64p r   = pack2(frcp(g0), frcp(g1));
                const u64p q   = mul2(r, mul2(p, s));       // 1/p
                const u64p iH  = mul2(r, mul2(p2, p2));     // mu/H
                const u64p t   = fma2(tmu2, xv, nmu2);      // mu(2x-1)
                const u64p f1  = fma2(t, q, fma2(lam2, wv, cP[idx]));
                const u64p wiH = mul2(wv, iH);
                qS[idx]  = q;
                iHS[idx] = iH;
                a1 = fma2(xv,  wv, a1);   // sum x w
                a2 = fma2(wiH, f1, a2);   // mu * sum (w/H) F1
                a3 = fma2(wiH, wv, a3);   // mu * sum w^2/H
            }
            float lo, hi;
            unpack2(a1, lo, hi); s1 = lo + hi;
            unpack2(a2, lo, hi); s2 = lo + hi;
            unpack2(a3, lo, hi); s3 = lo + hi;
        }
        s1 = wsum32(s1); s2 = wsum32(s2); s3 = wsum32(s3);
        if (lane == 0) { sA[wid] = s1; sB[wid] = s2; sC[wid] = s3; }
        __syncthreads();
        const float A = bsum16(sA[lane & 15]);
        const float Bv = bsum16(sB[lane & 15]);
        const float Cv = bsum16(sC[lane & 15]);
        const float dlam = (muc * (A - CAP) - Bv) * frcp(Cv);   // scalar Schur

        // ---- Pass B: mm = -mu*dx via lam' = lam+dlam; boundary ratio -------
        const float lampf = lam + dlam;
        const u64p lamp2 = pack2(lampf, lampf);
        u64p mmS[4];
        float tm = 0.0f;
#pragma unroll
        for (int idx = 0; idx < 4; idx++) {
            const u64p xv  = xP[idx];
            const u64p t   = fma2(tmu2, xv, nmu2);
            const u64p f   = fma2(t, qS[idx], fma2(lamp2, wP[idx], cP[idx]));
            const u64p mm  = mul2(f, iHS[idx]);               // -mu*dx
            mmS[idx] = mm;
            const u64p omx = fma2(xv, none2, one2);
            const u64p ta  = mul2(mm, mul2(omx, qS[idx]));    // mm/x
            const u64p tb  = mul2(mm, mul2(xv,  qS[idx]));    // mm/(1-x)
            float u0, u1, v0, v1;
            unpack2(ta, u0, u1); unpack2(tb, v0, v1);
            tm = fmaxf(tm, fmaxf(fmaxf(u0, u1), fmaxf(-v0, -v1)));
        }
        tm = wmax32(tm);
        if (lane == 0) sD[wid] = tm;
        __syncthreads();
        const float tmax = bmax16(sD[lane & 15]);

        const float alpha = (tmax > 0.0f) ? fminf(1.0f, 0.99f * muc * frcp(tmax)) : 1.0f;
        const float aom   = alpha * frcp(muc);
        const u64p na2 = pack2(-aom, -aom);
#pragma unroll
        for (int idx = 0; idx < 4; idx++)
            xP[idx] = fma2(na2, mmS[idx], xP[idx]);
        lam = fmaf(alpha, dlam, lam);

        // Early exit: mu pinned and relative step negligible (guards accuracy)
        if (muc <= DAMP) {
            if (tmax < 1e-6f * muc && fabsf(dlam) < 1e-6f * (1.0f + fabsf(lam)))
                break;
        }
    }

    // ---- KKT refine at mu = DAMP: out = x - mm/mu --------------------------
    {
        const float muc = DAMP;
        const u64p tmu2 = pack2(2.0f * muc, 2.0f * muc);
        const u64p nmu2 = pack2(-muc, -muc);
        const u64p lam2 = pack2(lam, lam);

        float s1, s2, s3;
        {
            u64p a1 = 0ull, a2 = 0ull, a3 = 0ull;
#pragma unroll
            for (int idx = 0; idx < 4; idx++) {
                const u64p xv  = xP[idx];
                const u64p wv  = wP[idx];
                const u64p omx = fma2(xv, none2, one2);
                const u64p p   = mul2(xv, omx);
                const u64p s   = fma2(p, n22, one2);
                const u64p p2  = mul2(p, p);
                const u64p arg = mul2(p2, s);
                float g0, g1; unpack2(arg, g0, g1);
                const u64p r   = pack2(frcp(g0), frcp(g1));
                const u64p q   = mul2(r, mul2(p, s));
                const u64p iH  = mul2(r, mul2(p2, p2));
                const u64p t   = fma2(tmu2, xv, nmu2);
                const u64p f1  = fma2(t, q, fma2(lam2, wv, cP[idx]));
                const u64p wiH = mul2(wv, iH);
                qS[idx]  = q;
                iHS[idx] = iH;
                a1 = fma2(xv,  wv, a1);
                a2 = fma2(wiH, f1, a2);
                a3 = fma2(wiH, wv, a3);
            }
            float lo, hi;
            unpack2(a1, lo, hi); s1 = lo + hi;
            unpack2(a2, lo, hi); s2 = lo + hi;
            unpack2(a3, lo, hi); s3 = lo + hi;
        }
        s1 = wsum32(s1); s2 = wsum32(s2); s3 = wsum32(s3);
        if (lane == 0) { sA[wid] = s1; sB[wid] = s2; sC[wid] = s3; }
        __syncthreads();
        const float A = bsum16(sA[lane & 15]);
        const float Bv = bsum16(sB[lane & 15]);
        const float Cv = bsum16(sC[lane & 15]);
        const float dlam = (muc * (A - CAP) - Bv) * frcp(Cv);

        const float lampf = lam + dlam;
        const u64p lamp2 = pack2(lampf, lampf);
        const float inv_mu = 1.0f / DAMP;
        const u64p ni2 = pack2(-inv_mu, -inv_mu);

        float4* orow = (float4*)(out + (size_t)blockIdx.x * NITEMS);
#pragma unroll
        for (int h = 0; h < 2; h++) {
            float4 o;
#pragma unroll
            for (int j = 0; j < 2; j++) {
                const int idx = h * 2 + j;
                const u64p xv = xP[idx];
                const u64p t  = fma2(tmu2, xv, nmu2);
                const u64p f  = fma2(t, qS[idx], fma2(lamp2, wP[idx], cP[idx]));
                const u64p mm = mul2(f, iHS[idx]);
                const u64p ov = fma2(ni2, mm, xv);     // x + dx
                float lo, hi; unpack2(ov, lo, hi);
                if (j == 0) { o.x = lo; o.y = hi; }
                else        { o.z = lo; o.w = hi; }
            }
            orow[h * TPB + tid] = o;
        }
    }
}

extern "C" void kernel_launch(void* const* d_in, const int* in_sizes, int n_in,
                              void* d_out, int out_size)
{
    const float* costs = (const float*)d_in[0];
    const float* wv    = (const float*)d_in[1];
    int costs_elems = in_sizes[0];
    if (n_in >= 2 && in_sizes[0] == NITEMS && in_sizes[1] > NITEMS) {
        costs = (const float*)d_in[1];
        wv    = (const float*)d_in[0];
        costs_elems = in_sizes[1];
    }
    const int B = costs_elems / NITEMS;
    ipm_kernel<<<B, TPB>>>(costs, wv, (float*)d_out);
}

// round 4
// speedup vs baseline: 1.2029x; 1.2029x over previous
#include <cuda_runtime.h>
#include <cstdint>

#define NITEMS 4096
#define TPB    512
#define NWARP  16
#define NIT    40
#define CAP    600.0f
#define DAMP   1e-3f

typedef unsigned long long u64p;   // packed f32x2

__device__ __forceinline__ float frcp(float v) {
    float r;
    asm("rcp.approx.ftz.f32 %0, %1;" : "=f"(r) : "f"(v));
    return r;
}
__device__ __forceinline__ u64p pack2(float lo, float hi) {
    u64p r;
    asm("mov.b64 %0, {%1, %2};" : "=l"(r) : "f"(lo), "f"(hi));
    return r;
}
__device__ __forceinline__ void unpack2(u64p v, float& lo, float& hi) {
    asm("mov.b64 {%0, %1}, %2;" : "=f"(lo), "=f"(hi) : "l"(v));
}
__device__ __forceinline__ u64p mul2(u64p a, u64p b) {
    u64p r;
    asm("mul.rn.f32x2 %0, %1, %2;" : "=l"(r) : "l"(a), "l"(b));
    return r;
}
__device__ __forceinline__ u64p fma2(u64p a, u64p b, u64p c) {
    u64p r;
    asm("fma.rn.f32x2 %0, %1, %2, %3;" : "=l"(r) : "l"(a), "l"(b), "l"(c));
    return r;
}

__device__ __forceinline__ float wsum32(float v) {
#pragma unroll
    for (int o = 16; o > 0; o >>= 1) v += __shfl_xor_sync(0xffffffffu, v, o);
    return v;
}
__device__ __forceinline__ float wmax32(float v) {
#pragma unroll
    for (int o = 16; o > 0; o >>= 1) v = fmaxf(v, __shfl_xor_sync(0xffffffffu, v, o));
    return v;
}
__device__ __forceinline__ float bsum16(float v) {
#pragma unroll
    for (int o = 8; o > 0; o >>= 1) v += __shfl_xor_sync(0xffffffffu, v, o);
    return v;
}
__device__ __forceinline__ float bmax16(float v) {
#pragma unroll
    for (int o = 8; o > 0; o >>= 1) v = fmaxf(v, __shfl_xor_sync(0xffffffffu, v, o));
    return v;
}

// Pass A: one rcp/elem. p=x(1-x), s=1-2p, r=1/(p^2 s) => 1/p = r p s, mu/H = r p^4
__device__ __forceinline__ void passA(
    const float4* __restrict__ sc, const float4* __restrict__ sw, int tid,
    const u64p* xP, u64p* qS, u64p* wiS, u64p* fiS,
    float lam, float muc, u64p one2, u64p none2, u64p n22,
    float& o1, float& o2, float& o3)
{
    const u64p lam2 = pack2(lam, lam);
    const u64p tmu2 = pack2(2.0f * muc, 2.0f * muc);
    const u64p nmu2 = pack2(-muc, -muc);
    u64p s1 = 0ull, s2 = 0ull, s3 = 0ull;
#pragma unroll
    for (int h = 0; h < 2; h++) {
        const float4 cf = sc[h * TPB + tid];
        const float4 wf = sw[h * TPB + tid];
#pragma unroll
        for (int j = 0; j < 2; j++) {
            const int idx = h * 2 + j;
            const u64p cv = j ? pack2(cf.z, cf.w) : pack2(cf.x, cf.y);
            const u64p wv = j ? pack2(wf.z, wf.w) : pack2(wf.x, wf.y);
            const u64p xv = xP[idx];
            const u64p omx = fma2(xv, none2, one2);
            const u64p p   = mul2(xv, omx);
            const u64p s   = fma2(p, n22, one2);
            const u64p p2  = mul2(p, p);
            const u64p arg = mul2(p2, s);
            float a0, a1; unpack2(arg, a0, a1);
            const u64p r   = pack2(frcp(a0), frcp(a1));
            const u64p q   = mul2(r, mul2(p, s));
            const u64p iH  = mul2(r, mul2(p2, p2));
            const u64p t   = fma2(tmu2, xv, nmu2);
            const u64p f1  = fma2(t, q, fma2(lam2, wv, cv));
            const u64p wiH = mul2(wv, iH);
            qS[idx]  = q;
            wiS[idx] = wiH;
            fiS[idx] = mul2(f1, iH);
            s1 = fma2(xv,  wv, s1);
            s2 = fma2(wiH, f1, s2);
            s3 = fma2(wiH, wv, s3);
        }
    }
    float lo, hi;
    unpack2(s1, lo, hi); o1 = lo + hi;
    unpack2(s2, lo, hi); o2 = lo + hi;
    unpack2(s3, lo, hi); o3 = lo + hi;
}

// Pass B: per-thread boundary ratio max;  mm = -mu*dx = fiS + dlam*wiS
__device__ __forceinline__ float passB(
    const u64p* xP, const u64p* qS, const u64p* wiS, const u64p* fiS,
    float dlam, u64p one2, u64p none2)
{
    const u64p dl2 = pack2(dlam, dlam);
    float tm = 0.0f;
#pragma unroll
    for (int idx = 0; idx < 4; idx++) {
        const u64p mm  = fma2(dl2, wiS[idx], fiS[idx]);
        const u64p omx = fma2(xP[idx], none2, one2);
        const u64p ta  = mul2(mm, mul2(omx, qS[idx]));      // mm/x
        const u64p tb  = mul2(mm, mul2(xP[idx], qS[idx]));  // mm/(1-x)
        float u0, u1, v0, v1;
        unpack2(ta, u0, u1); unpack2(tb, v0, v1);
        tm = fmaxf(tm, fmaxf(fmaxf(u0, u1), fmaxf(-v0, -v1)));
    }
    return tm;
}

__global__ void __launch_bounds__(TPB, 1)
ipm_kernel(const float* __restrict__ costs,
           const float* __restrict__ wglob,
           float* __restrict__ out)
{
    __shared__ float4 sc0[2 * TPB];            // -costs row 0 (16KB)
    __shared__ float4 sc1[2 * TPB];            // -costs row 1 (16KB)
    __shared__ float4 sw[2 * TPB];             // weights      (16KB)
    __shared__ float sA[2][NWARP], sB[2][NWARP], sC[2][NWARP], sD[2][NWARP];

    const int tid = threadIdx.x, lane = tid & 31, wid = tid >> 5;
    const size_t row0 = (size_t)blockIdx.x * 2;

    float wsum;
    {
        const float4* cg0 = (const float4*)(costs + row0 * NITEMS);
        const float4* cg1 = (const float4*)(costs + (row0 + 1) * NITEMS);
        const float4* wg  = (const float4*)wglob;
        wsum = 0.0f;
#pragma unroll
        for (int h = 0; h < 2; h++) {
            const float4 a = cg0[h * TPB + tid];
            const float4 b = cg1[h * TPB + tid];
            const float4 w = wg[h * TPB + tid];
            sc0[h * TPB + tid] = make_float4(-a.x, -a.y, -a.z, -a.w);
            sc1[h * TPB + tid] = make_float4(-b.x, -b.y, -b.z, -b.w);
            sw[h * TPB + tid] = w;
            wsum += (w.x + w.y) + (w.z + w.w);
        }
    }
    wsum = wsum32(wsum);
    if (lane == 0) sA[0][wid] = wsum;
    __syncthreads();
    wsum = bsum16(sA[0][lane & 15]);
    __syncthreads();                 // protect sA reuse in iteration 0

    const float x0 = CAP * frcp(wsum);

    u64p xP0[4], qS0[4], wiS0[4], fiS0[4];
    u64p xP1[4], qS1[4], wiS1[4], fiS1[4];
#pragma unroll
    for (int i = 0; i < 4; i++) { xP0[i] = pack2(x0, x0); xP1[i] = pack2(x0, x0); }

    const u64p one2  = pack2(1.0f, 1.0f);
    const u64p none2 = pack2(-1.0f, -1.0f);
    const u64p n22   = pack2(-2.0f, -2.0f);

    float lam0 = 0.0f, lam1 = 0.0f, mupow = 1.0f;

#pragma unroll 1
    for (int it = 0; it < NIT; ++it) {
        const float muc = fmaxf(mupow, DAMP);
        mupow *= 0.5f;

        // ---- Pass A both rows (independent -> ILP across rows) -------------
        float r0s1, r0s2, r0s3, r1s1, r1s2, r1s3;
        passA(sc0, sw, tid, xP0, qS0, wiS0, fiS0, lam0, muc, one2, none2, n22, r0s1, r0s2, r0s3);
        passA(sc1, sw, tid, xP1, qS1, wiS1, fiS1, lam1, muc, one2, none2, n22, r1s1, r1s2, r1s3);

        r0s1 = wsum32(r0s1); r0s2 = wsum32(r0s2); r0s3 = wsum32(r0s3);
        r1s1 = wsum32(r1s1); r1s2 = wsum32(r1s2); r1s3 = wsum32(r1s3);
        if (lane == 0) {
            sA[0][wid] = r0s1; sB[0][wid] = r0s2; sC[0][wid] = r0s3;
            sA[1][wid] = r1s1; sB[1][wid] = r1s2; sC[1][wid] = r1s3;
        }
        __syncthreads();
        const float A0 = bsum16(sA[0][lane & 15]);
        const float B0 = bsum16(sB[0][lane & 15]);
        const float C0 = bsum16(sC[0][lane & 15]);
        const float A1 = bsum16(sA[1][lane & 15]);
        const float B1 = bsum16(sB[1][lane & 15]);
        const float C1 = bsum16(sC[1][lane & 15]);
        const float dlam0 = (muc * (A0 - CAP) - B0) * frcp(C0);
        const float dlam1 = (muc * (A1 - CAP) - B1) * frcp(C1);

        // ---- Pass B both rows ----------------------------------------------
        float tm0 = passB(xP0, qS0, wiS0, fiS0, dlam0, one2, none2);
        float tm1 = passB(xP1, qS1, wiS1, fiS1, dlam1, one2, none2);
        tm0 = wmax32(tm0); tm1 = wmax32(tm1);
        if (lane == 0) { sD[0][wid] = tm0; sD[1][wid] = tm1; }
        __syncthreads();
        const float tmax0 = bmax16(sD[0][lane & 15]);
        const float tmax1 = bmax16(sD[1][lane & 15]);

        const float alpha0 = (tmax0 > 0.0f) ? fminf(1.0f, 0.99f * muc * frcp(tmax0)) : 1.0f;
        const float alpha1 = (tmax1 > 0.0f) ? fminf(1.0f, 0.99f * muc * frcp(tmax1)) : 1.0f;
        const float aom0 = alpha0 * frcp(muc);
        const float aom1 = alpha1 * frcp(muc);
        const u64p dl20 = pack2(dlam0, dlam0), na20 = pack2(-aom0, -aom0);
        const u64p dl21 = pack2(dlam1, dlam1), na21 = pack2(-aom1, -aom1);
#pragma unroll
        for (int idx = 0; idx < 4; idx++) {
            xP0[idx] = fma2(na20, fma2(dl20, wiS0[idx], fiS0[idx]), xP0[idx]);
            xP1[idx] = fma2(na21, fma2(dl21, wiS1[idx], fiS1[idx]), xP1[idx]);
        }
        lam0 = fmaf(alpha0, dlam0, lam0);
        lam1 = fmaf(alpha1, dlam1, lam1);

        // Early exit: mu pinned, both rows' relative steps negligible.
        if (muc <= DAMP) {
            const bool ok0 = tmax0 < 1e-5f * muc && fabsf(dlam0) < 1e-5f * (1.0f + fabsf(lam0));
            const bool ok1 = tmax1 < 1e-5f * muc && fabsf(dlam1) < 1e-5f * (1.0f + fabsf(lam1));
            if (ok0 && ok1) break;
        }
    }

    // ---- KKT refine at mu = DAMP: out = x + dx = x - mm/mu -----------------
    {
        float r0s1, r0s2, r0s3, r1s1, r1s2, r1s3;
        passA(sc0, sw, tid, xP0, qS0, wiS0, fiS0, lam0, DAMP, one2, none2, n22, r0s1, r0s2, r0s3);
        passA(sc1, sw, tid, xP1, qS1, wiS1, fiS1, lam1, DAMP, one2, none2, n22, r1s1, r1s2, r1s3);
        r0s1 = wsum32(r0s1); r0s2 = wsum32(r0s2); r0s3 = wsum32(r0s3);
        r1s1 = wsum32(r1s1); r1s2 = wsum32(r1s2); r1s3 = wsum32(r1s3);
        if (lane == 0) {
            sA[0][wid] = r0s1; sB[0][wid] = r0s2; sC[0][wid] = r0s3;
            sA[1][wid] = r1s1; sB[1][wid] = r1s2; sC[1][wid] = r1s3;
        }
        __syncthreads();
        const float A0 = bsum16(sA[0][lane & 15]);
        const float B0 = bsum16(sB[0][lane & 15]);
        const float C0 = bsum16(sC[0][lane & 15]);
        const float A1 = bsum16(sA[1][lane & 15]);
        const float B1 = bsum16(sB[1][lane & 15]);
        const float C1 = bsum16(sC[1][lane & 15]);
        const float dlam0 = (DAMP * (A0 - CAP) - B0) * frcp(C0);
        const float dlam1 = (DAMP * (A1 - CAP) - B1) * frcp(C1);

        const float inv_mu = 1.0f / DAMP;
        const u64p ni2 = pack2(-inv_mu, -inv_mu);
        const u64p dl20 = pack2(dlam0, dlam0);
        const u64p dl21 = pack2(dlam1, dlam1);

        float4* o0 = (float4*)(out + row0 * NITEMS);
        float4* o1 = (float4*)(out + (row0 + 1) * NITEMS);
#pragma unroll
        for (int h = 0; h < 2; h++) {
            float4 v0, v1;
#pragma unroll
            for (int j = 0; j < 2; j++) {
                const int idx = h * 2 + j;
                const u64p mm0 = fma2(dl20, wiS0[idx], fiS0[idx]);
                const u64p mm1 = fma2(dl21, wiS1[idx], fiS1[idx]);
                const u64p w0 = fma2(ni2, mm0, xP0[idx]);
                const u64p w1 = fma2(ni2, mm1, xP1[idx]);
                float lo, hi;
                if (j == 0) { unpack2(w0, v0.x, v0.y); unpack2(w1, v1.x, v1.y); }
                else        { unpack2(w0, lo, hi); v0.z = lo; v0.w = hi;
                              unpack2(w1, lo, hi); v1.z = lo; v1.w = hi; }
            }
            o0[h * TPB + tid] = v0;
            o1[h * TPB + tid] = v1;
        }
    }
}

extern "C" void kernel_launch(void* const* d_in, const int* in_sizes, int n_in,
                              void* d_out, int out_size)
{
    const float* costs = (const float*)d_in[0];
    const float* wv    = (const float*)d_in[1];
    int costs_elems = in_sizes[0];
    if (n_in >= 2 && in_sizes[0] == NITEMS && in_sizes[1] > NITEMS) {
        costs = (const float*)d_in[1];
        wv    = (const float*)d_in[0];
        costs_elems = in_sizes[1];
    }
    const int B = costs_elems / NITEMS;
    ipm_kernel<<<B / 2, TPB>>>(costs, wv, (float*)d_out);
}

// round 5
// speedup vs baseline: 1.2140x; 1.0092x over previous
#include <cuda_runtime.h>
#include <cstdint>

#define NITEMS 4096
#define TPB    512
#define NWARP  16
#define NIT    40
#define CAP    600.0f
#define DAMP   1e-3f

typedef unsigned long long u64p;   // packed f32x2

__device__ __forceinline__ float frcp(float v) {
    float r;
    asm("rcp.approx.ftz.f32 %0, %1;" : "=f"(r) : "f"(v));
    return r;
}
__device__ __forceinline__ u64p pack2(float lo, float hi) {
    u64p r;
    asm("mov.b64 %0, {%1, %2};" : "=l"(r) : "f"(lo), "f"(hi));
    return r;
}
__device__ __forceinline__ void unpack2(u64p v, float& lo, float& hi) {
    asm("mov.b64 {%0, %1}, %2;" : "=f"(lo), "=f"(hi) : "l"(v));
}
__device__ __forceinline__ u64p mul2(u64p a, u64p b) {
    u64p r;
    asm("mul.rn.f32x2 %0, %1, %2;" : "=l"(r) : "l"(a), "l"(b));
    return r;
}
__device__ __forceinline__ u64p fma2(u64p a, u64p b, u64p c) {
    u64p r;
    asm("fma.rn.f32x2 %0, %1, %2, %3;" : "=l"(r) : "l"(a), "l"(b), "l"(c));
    return r;
}

__device__ __forceinline__ float wsum32(float v) {
#pragma unroll
    for (int o = 16; o > 0; o >>= 1) v += __shfl_xor_sync(0xffffffffu, v, o);
    return v;
}
__device__ __forceinline__ float wmax32(float v) {
#pragma unroll
    for (int o = 16; o > 0; o >>= 1) v = fmaxf(v, __shfl_xor_sync(0xffffffffu, v, o));
    return v;
}
// reduce 16 per-warp partials duplicated across the warp (idx = lane&15)
__device__ __forceinline__ float bsum16(float v) {
#pragma unroll
    for (int o = 8; o > 0; o >>= 1) v += __shfl_xor_sync(0xffffffffu, v, o);
    return v;
}
__device__ __forceinline__ float bmax16(float v) {
#pragma unroll
    for (int o = 8; o > 0; o >>= 1) v = fmaxf(v, __shfl_xor_sync(0xffffffffu, v, o));
    return v;
}

// Pass A: one rcp per element.
//   p = x(1-x), s = 1-2p, r = 1/(p^2 s)  =>  1/p = r p s,  mu/H = p^2/s = r p^4
__device__ __forceinline__ void passA(
    const float4* __restrict__ sc, const float4* __restrict__ sw, int tid,
    const u64p* xP, u64p* qS, u64p* wiS, u64p* fiS,
    float lam, float muc, u64p one2, u64p none2, u64p n22,
    float& o1, float& o2, float& o3)
{
    const u64p lam2 = pack2(lam, lam);
    const u64p tmu2 = pack2(2.0f * muc, 2.0f * muc);
    const u64p nmu2 = pack2(-muc, -muc);
    u64p s1 = 0ull, s2 = 0ull, s3 = 0ull;
#pragma unroll
    for (int h = 0; h < 2; h++) {
        const float4 cf = sc[h * TPB + tid];
        const float4 wf = sw[h * TPB + tid];
#pragma unroll
        for (int j = 0; j < 2; j++) {
            const int idx = h * 2 + j;
            const u64p cv = j ? pack2(cf.z, cf.w) : pack2(cf.x, cf.y);
            const u64p wv = j ? pack2(wf.z, wf.w) : pack2(wf.x, wf.y);
            const u64p xv = xP[idx];
            const u64p omx = fma2(xv, none2, one2);     // 1-x
            const u64p p   = mul2(xv, omx);             // x(1-x)
            const u64p s   = fma2(p, n22, one2);        // 1-2p
            const u64p p2  = mul2(p, p);
            const u64p arg = mul2(p2, s);
            float a0, a1; unpack2(arg, a0, a1);
            const u64p r   = pack2(frcp(a0), frcp(a1)); // 1/(p^2 s)
            const u64p q   = mul2(r, mul2(p, s));       // 1/p
            const u64p iH  = mul2(r, mul2(p2, p2));     // mu/H
            const u64p t   = fma2(tmu2, xv, nmu2);      // mu(2x-1)
            const u64p f1  = fma2(t, q, fma2(lam2, wv, cv));
            const u64p wiH = mul2(wv, iH);
            qS[idx]  = q;
            wiS[idx] = wiH;
            fiS[idx] = mul2(f1, iH);
            s1 = fma2(xv,  wv, s1);    // sum x w
            s2 = fma2(wiH, f1, s2);    // mu * sum (w/H) F1
            s3 = fma2(wiH, wv, s3);    // mu * sum w^2/H
        }
    }
    float lo, hi;
    unpack2(s1, lo, hi); o1 = lo + hi;
    unpack2(s2, lo, hi); o2 = lo + hi;
    unpack2(s3, lo, hi); o3 = lo + hi;
}

__device__ __forceinline__ float reduce_dlam(
    float s1, float s2, float s3, float muc,
    float* sA, float* sB, float* sC, int lane, int wid)
{
    s1 = wsum32(s1); s2 = wsum32(s2); s3 = wsum32(s3);
    if (lane == 0) { sA[wid] = s1; sB[wid] = s2; sC[wid] = s3; }
    __syncthreads();
    const float a = bsum16(sA[lane & 15]);
    const float b = bsum16(sB[lane & 15]);
    const float c = bsum16(sC[lane & 15]);
    return (muc * (a - CAP) - b) * frcp(c);   // scalar Schur
}

__global__ void __launch_bounds__(TPB, 2)
ipm_kernel(const float* __restrict__ costs,
           const float* __restrict__ wglob,
           float* __restrict__ out)
{
    __shared__ float4 sc[2 * TPB];   // -costs row, 16KB
    __shared__ float4 sw[2 * TPB];   // weights,    16KB
    __shared__ float sA[NWARP], sB[NWARP], sC[NWARP], sD[NWARP];

    const int tid = threadIdx.x, lane = tid & 31, wid = tid >> 5;
    const float* crow = costs + (size_t)blockIdx.x * NITEMS;

    float wsum;
    {
        const float4* cg = (const float4*)crow;
        const float4* wg = (const float4*)wglob;
        const float4 c0 = cg[tid], c1 = cg[TPB + tid];
        const float4 w0 = wg[tid], w1 = wg[TPB + tid];
        sc[tid]       = make_float4(-c0.x, -c0.y, -c0.z, -c0.w);
        sc[TPB + tid] = make_float4(-c1.x, -c1.y, -c1.z, -c1.w);
        sw[tid] = w0; sw[TPB + tid] = w1;
        wsum = ((w0.x + w0.y) + (w0.z + w0.w)) + ((w1.x + w1.y) + (w1.z + w1.w));
    }
    wsum = wsum32(wsum);
    if (lane == 0) sA[wid] = wsum;
    __syncthreads();
    wsum = bsum16(sA[lane & 15]);
    __syncthreads();   // protect sA reuse in iteration 0

    const float x0 = CAP * frcp(wsum);   // equality-feasible interior start

    u64p xP[4], qS[4], wiS[4], fiS[4];
#pragma unroll
    for (int i = 0; i < 4; i++) xP[i] = pack2(x0, x0);

    const u64p one2  = pack2(1.0f, 1.0f);
    const u64p none2 = pack2(-1.0f, -1.0f);
    const u64p n22   = pack2(-2.0f, -2.0f);

    float lam = 0.0f, mupow = 1.0f;

#pragma unroll 1
    for (int it = 0; it < NIT; ++it) {
        const float muc = fmaxf(mupow, DAMP);
        mupow *= 0.25f;              // aggressive path: mu pinned after 5 iters

        float s1, s2, s3;
        passA(sc, sw, tid, xP, qS, wiS, fiS, lam, muc, one2, none2, n22, s1, s2, s3);
        const float dlam = reduce_dlam(s1, s2, s3, muc, sA, sB, sC, lane, wid);
        const u64p dl2 = pack2(dlam, dlam);

        // fraction-to-boundary: mm = -mu*dx; ratios via stored q = 1/(x(1-x))
        float tm = 0.0f;
#pragma unroll
        for (int idx = 0; idx < 4; idx++) {
            const u64p mm  = fma2(dl2, wiS[idx], fiS[idx]);
            const u64p omx = fma2(xP[idx], none2, one2);
            const u64p t1  = mul2(mm, mul2(omx, qS[idx]));      // mm/x
            const u64p t2  = mul2(mm, mul2(xP[idx], qS[idx]));  // mm/(1-x)
            float u0, u1, v0, v1;
            unpack2(t1, u0, u1); unpack2(t2, v0, v1);
            tm = fmaxf(tm, fmaxf(fmaxf(u0, u1), fmaxf(-v0, -v1)));
        }
        tm = wmax32(tm);
        if (lane == 0) sD[wid] = tm;
        __syncthreads();
        const float tmax = bmax16(sD[lane & 15]);

        const float alpha = (tmax > 0.0f) ? fminf(1.0f, 0.99f * muc * frcp(tmax)) : 1.0f;
        const float aom   = alpha * frcp(muc);
        const u64p na2 = pack2(-aom, -aom);
#pragma unroll
        for (int idx = 0; idx < 4; idx++) {
            const u64p mm = fma2(dl2, wiS[idx], fiS[idx]);
            xP[idx] = fma2(na2, mm, xP[idx]);
        }
        lam = fmaf(alpha, dlam, lam);

        // Early exit once mu is pinned and the relative step is negligible.
        if (muc <= DAMP) {
            if (tmax < 1e-5f * muc && fabsf(dlam) < 1e-5f * (1.0f + fabsf(lam)))
                break;
        }
    }

    // KKT refine at mu = DAMP: out = x + dx = x - mm/mu
    {
        float s1, s2, s3;
        passA(sc, sw, tid, xP, qS, wiS, fiS, lam, DAMP, one2, none2, n22, s1, s2, s3);
        const float dlam = reduce_dlam(s1, s2, s3, DAMP, sA, sB, sC, lane, wid);
        const u64p dl2 = pack2(dlam, dlam);
        const float inv_mu = 1.0f / DAMP;
        const u64p ni2 = pack2(-inv_mu, -inv_mu);

        float4* orow = (float4*)(out + (size_t)blockIdx.x * NITEMS);
#pragma unroll
        for (int h = 0; h < 2; h++) {
            float4 o;
            {
                const int idx = h * 2;
                const u64p mm = fma2(dl2, wiS[idx], fiS[idx]);
                const u64p ov = fma2(ni2, mm, xP[idx]);
                unpack2(ov, o.x, o.y);
            }
            {
                const int idx = h * 2 + 1;
                const u64p mm = fma2(dl2, wiS[idx], fiS[idx]);
                const u64p ov = fma2(ni2, mm, xP[idx]);
                unpack2(ov, o.z, o.w);
            }
            orow[h * TPB + tid] = o;
        }
    }
}

extern "C" void kernel_launch(void* const* d_in, const int* in_sizes, int n_in,
                              void* d_out, int out_size)
{
    const float* costs = (const float*)d_in[0];
    const float* wv    = (const float*)d_in[1];
    int costs_elems = in_sizes[0];
    if (n_in >= 2 && in_sizes[0] == NITEMS && in_sizes[1] > NITEMS) {
        costs = (const float*)d_in[1];
        wv    = (const float*)d_in[0];
        costs_elems = in_sizes[1];
    }
    const int B = costs_elems / NITEMS;
    ipm_kernel<<<B, TPB>>>(costs, wv, (float*)d_out);
}

// round 6
// speedup vs baseline: 1.3599x; 1.1202x over previous
#include <cuda_runtime.h>
#include <cstdint>

#define NITEMS 4096
#define TPB    512
#define NWARP  16
#define NIT    40
#define CAP    600.0f
#define DAMP   1e-3f
#define XTOL   1e-4f     // relative-step exit tolerance (noise floor ~1e-5)

typedef unsigned long long u64p;   // packed f32x2

__device__ __forceinline__ float frcp(float v) {
    float r;
    asm("rcp.approx.ftz.f32 %0, %1;" : "=f"(r) : "f"(v));
    return r;
}
__device__ __forceinline__ u64p pack2(float lo, float hi) {
    u64p r;
    asm("mov.b64 %0, {%1, %2};" : "=l"(r) : "f"(lo), "f"(hi));
    return r;
}
__device__ __forceinline__ void unpack2(u64p v, float& lo, float& hi) {
    asm("mov.b64 {%0, %1}, %2;" : "=f"(lo), "=f"(hi) : "l"(v));
}
__device__ __forceinline__ u64p mul2(u64p a, u64p b) {
    u64p r;
    asm("mul.rn.f32x2 %0, %1, %2;" : "=l"(r) : "l"(a), "l"(b));
    return r;
}
__device__ __forceinline__ u64p fma2(u64p a, u64p b, u64p c) {
    u64p r;
    asm("fma.rn.f32x2 %0, %1, %2, %3;" : "=l"(r) : "l"(a), "l"(b), "l"(c));
    return r;
}

__device__ __forceinline__ float wsum32(float v) {
#pragma unroll
    for (int o = 16; o > 0; o >>= 1) v += __shfl_xor_sync(0xffffffffu, v, o);
    return v;
}
__device__ __forceinline__ float wmax32(float v) {
#pragma unroll
    for (int o = 16; o > 0; o >>= 1) v = fmaxf(v, __shfl_xor_sync(0xffffffffu, v, o));
    return v;
}
// reduce 16 per-warp partials duplicated across the warp (idx = lane&15)
__device__ __forceinline__ float bsum16(float v) {
#pragma unroll
    for (int o = 8; o > 0; o >>= 1) v += __shfl_xor_sync(0xffffffffu, v, o);
    return v;
}
__device__ __forceinline__ float bmax16(float v) {
#pragma unroll
    for (int o = 8; o > 0; o >>= 1) v = fmaxf(v, __shfl_xor_sync(0xffffffffu, v, o));
    return v;
}

// Pass A: one rcp per element.
//   p = x(1-x), s = 1-2p, r = 1/(p^2 s)  =>  1/p = r p s,  mu/H = p^2/s = r p^4
__device__ __forceinline__ void passA(
    const float4* __restrict__ sc, const float4* __restrict__ sw, int tid,
    const u64p* xP, u64p* qS, u64p* wiS, u64p* fiS,
    float lam, float muc, u64p one2, u64p none2, u64p n22,
    float& o1, float& o2, float& o3)
{
    const u64p lam2 = pack2(lam, lam);
    const u64p tmu2 = pack2(2.0f * muc, 2.0f * muc);
    const u64p nmu2 = pack2(-muc, -muc);
    u64p s1 = 0ull, s2 = 0ull, s3 = 0ull;
#pragma unroll
    for (int h = 0; h < 2; h++) {
        const float4 cf = sc[h * TPB + tid];
        const float4 wf = sw[h * TPB + tid];
#pragma unroll
        for (int j = 0; j < 2; j++) {
            const int idx = h * 2 + j;
            const u64p cv = j ? pack2(cf.z, cf.w) : pack2(cf.x, cf.y);
            const u64p wv = j ? pack2(wf.z, wf.w) : pack2(wf.x, wf.y);
            const u64p xv = xP[idx];
            const u64p omx = fma2(xv, none2, one2);     // 1-x
            const u64p p   = mul2(xv, omx);             // x(1-x)
            const u64p s   = fma2(p, n22, one2);        // 1-2p
            const u64p p2  = mul2(p, p);
            const u64p arg = mul2(p2, s);
            float a0, a1; unpack2(arg, a0, a1);
            const u64p r   = pack2(frcp(a0), frcp(a1)); // 1/(p^2 s)
            const u64p q   = mul2(r, mul2(p, s));       // 1/p
            const u64p iH  = mul2(r, mul2(p2, p2));     // mu/H
            const u64p t   = fma2(tmu2, xv, nmu2);      // mu(2x-1)
            const u64p f1  = fma2(t, q, fma2(lam2, wv, cv));
            const u64p wiH = mul2(wv, iH);
            qS[idx]  = q;
            wiS[idx] = wiH;
            fiS[idx] = mul2(f1, iH);
            s1 = fma2(xv,  wv, s1);    // sum x w
            s2 = fma2(wiH, f1, s2);    // mu * sum (w/H) F1
            s3 = fma2(wiH, wv, s3);    // mu * sum w^2/H
        }
    }
    float lo, hi;
    unpack2(s1, lo, hi); o1 = lo + hi;
    unpack2(s2, lo, hi); o2 = lo + hi;
    unpack2(s3, lo, hi); o3 = lo + hi;
}

__device__ __forceinline__ float reduce_dlam(
    float s1, float s2, float s3, float muc,
    float* sA, float* sB, float* sC, int lane, int wid)
{
    s1 = wsum32(s1); s2 = wsum32(s2); s3 = wsum32(s3);
    if (lane == 0) { sA[wid] = s1; sB[wid] = s2; sC[wid] = s3; }
    __syncthreads();
    const float a = bsum16(sA[lane & 15]);
    const float b = bsum16(sB[lane & 15]);
    const float c = bsum16(sC[lane & 15]);
    return (muc * (a - CAP) - b) * frcp(c);   // scalar Schur
}

__global__ void __launch_bounds__(TPB, 2)
ipm_kernel(const float* __restrict__ costs,
           const float* __restrict__ wglob,
           float* __restrict__ out)
{
    __shared__ float4 sc[2 * TPB];   // -costs row, 16KB
    __shared__ float4 sw[2 * TPB];   // weights,    16KB
    __shared__ float sA[NWARP], sB[NWARP], sC[NWARP], sD[NWARP];

    const int tid = threadIdx.x, lane = tid & 31, wid = tid >> 5;
    const float* crow = costs + (size_t)blockIdx.x * NITEMS;

    float wsum;
    {
        const float4* cg = (const float4*)crow;
        const float4* wg = (const float4*)wglob;
        const float4 c0 = cg[tid], c1 = cg[TPB + tid];
        const float4 w0 = wg[tid], w1 = wg[TPB + tid];
        sc[tid]       = make_float4(-c0.x, -c0.y, -c0.z, -c0.w);
        sc[TPB + tid] = make_float4(-c1.x, -c1.y, -c1.z, -c1.w);
        sw[tid] = w0; sw[TPB + tid] = w1;
        wsum = ((w0.x + w0.y) + (w0.z + w0.w)) + ((w1.x + w1.y) + (w1.z + w1.w));
    }
    wsum = wsum32(wsum);
    if (lane == 0) sA[wid] = wsum;
    __syncthreads();
    wsum = bsum16(sA[lane & 15]);
    __syncthreads();   // protect sA reuse in iteration 0

    const float x0 = CAP * frcp(wsum);   // equality-feasible interior start

    u64p xP[4], qS[4], wiS[4], fiS[4];
#pragma unroll
    for (int i = 0; i < 4; i++) xP[i] = pack2(x0, x0);

    const u64p one2  = pack2(1.0f, 1.0f);
    const u64p none2 = pack2(-1.0f, -1.0f);
    const u64p n22   = pack2(-2.0f, -2.0f);

    float lam = 0.0f, mupow = 1.0f;

#pragma unroll 1
    for (int it = 0; it < NIT; ++it) {
        const float muc = fmaxf(mupow, DAMP);
        mupow *= 0.25f;              // aggressive path: mu pinned after 5 iters

        float s1, s2, s3;
        passA(sc, sw, tid, xP, qS, wiS, fiS, lam, muc, one2, none2, n22, s1, s2, s3);
        const float dlam = reduce_dlam(s1, s2, s3, muc, sA, sB, sC, lane, wid);
        const u64p dl2 = pack2(dlam, dlam);

        // fraction-to-boundary: mm = -mu*dx; ratios via stored q = 1/(x(1-x))
        float tm = 0.0f;
#pragma unroll
        for (int idx = 0; idx < 4; idx++) {
            const u64p mm  = fma2(dl2, wiS[idx], fiS[idx]);
            const u64p omx = fma2(xP[idx], none2, one2);
            const u64p t1  = mul2(mm, mul2(omx, qS[idx]));      // mm/x
            const u64p t2  = mul2(mm, mul2(xP[idx], qS[idx]));  // mm/(1-x)
            float u0, u1, v0, v1;
            unpack2(t1, u0, u1); unpack2(t2, v0, v1);
            tm = fmaxf(tm, fmaxf(fmaxf(u0, u1), fmaxf(-v0, -v1)));
        }
        tm = wmax32(tm);
        if (lane == 0) sD[wid] = tm;
        __syncthreads();
        const float tmax = bmax16(sD[lane & 15]);

        const float alpha = (tmax > 0.0f) ? fminf(1.0f, 0.99f * muc * frcp(tmax)) : 1.0f;
        const float aom   = alpha * frcp(muc);
        const u64p na2 = pack2(-aom, -aom);
#pragma unroll
        for (int idx = 0; idx < 4; idx++) {
            const u64p mm = fma2(dl2, wiS[idx], fiS[idx]);
            xP[idx] = fma2(na2, mm, xP[idx]);
        }
        lam = fmaf(alpha, dlam, lam);

        // Exit once mu is pinned and the Newton step is < XTOL relative.
        // (tmax = mu * max relative step, so compare against XTOL*muc.)
        if (muc <= DAMP) {
            if (tmax < XTOL * muc && fabsf(dlam) < XTOL * (1.0f + fabsf(lam)))
                break;
        }
    }

    // KKT refine at mu = DAMP: out = x + dx = x - mm/mu
    {
        float s1, s2, s3;
        passA(sc, sw, tid, xP, qS, wiS, fiS, lam, DAMP, one2, none2, n22, s1, s2, s3);
        const float dlam = reduce_dlam(s1, s2, s3, DAMP, sA, sB, sC, lane, wid);
        const u64p dl2 = pack2(dlam, dlam);
        const float inv_mu = 1.0f / DAMP;
        const u64p ni2 = pack2(-inv_mu, -inv_mu);

        float4* orow = (float4*)(out + (size_t)blockIdx.x * NITEMS);
#pragma unroll
        for (int h = 0; h < 2; h++) {
            float4 o;
            {
                const int idx = h * 2;
                const u64p mm = fma2(dl2, wiS[idx], fiS[idx]);
                const u64p ov = fma2(ni2, mm, xP[idx]);
                unpack2(ov, o.x, o.y);
            }
            {
                const int idx = h * 2 + 1;
                const u64p mm = fma2(dl2, wiS[idx], fiS[idx]);
                const u64p ov = fma2(ni2, mm, xP[idx]);
                unpack2(ov, o.z, o.w);
            }
            orow[h * TPB + tid] = o;
        }
    }
}

extern "C" void kernel_launch(void* const* d_in, const int* in_sizes, int n_in,
                              void* d_out, int out_size)
{
    const float* costs = (const float*)d_in[0];
    const float* wv    = (const float*)d_in[1];
    int costs_elems = in_sizes[0];
    if (n_in >= 2 && in_sizes[0] == NITEMS && in_sizes[1] > NITEMS) {
        costs = (const float*)d_in[1];
        wv    = (const float*)d_in[0];
        costs_elems = in_sizes[1];
    }
    const int B = costs_elems / NITEMS;
    ipm_kernel<<<B, TPB>>>(costs, wv, (float*)d_out);
}

// round 7
// speedup vs baseline: 6.8116x; 5.0089x over previous
#include <cuda_runtime.h>
#include <cstdint>

#define NITEMS 4096
#define TPB    512
#define NWARP  16
#define CAP    600.0f
#define MU     1e-3f
#define MAXIT  24

typedef unsigned long long u64p;   // packed f32x2

__device__ __forceinline__ float frcp(float v) {
    float r;
    asm("rcp.approx.ftz.f32 %0, %1;" : "=f"(r) : "f"(v));
    return r;
}
__device__ __forceinline__ float frsq(float v) {
    float r;
    asm("rsqrt.approx.ftz.f32 %0, %1;" : "=f"(r) : "f"(v));
    return r;
}
__device__ __forceinline__ u64p pack2(float lo, float hi) {
    u64p r;
    asm("mov.b64 %0, {%1, %2};" : "=l"(r) : "f"(lo), "f"(hi));
    return r;
}
__device__ __forceinline__ void unpack2(u64p v, float& lo, float& hi) {
    asm("mov.b64 {%0, %1}, %2;" : "=f"(lo), "=f"(hi) : "l"(v));
}
__device__ __forceinline__ u64p mul2(u64p a, u64p b) {
    u64p r;
    asm("mul.rn.f32x2 %0, %1, %2;" : "=l"(r) : "l"(a), "l"(b));
    return r;
}
__device__ __forceinline__ u64p fma2(u64p a, u64p b, u64p c) {
    u64p r;
    asm("fma.rn.f32x2 %0, %1, %2, %3;" : "=l"(r) : "l"(a), "l"(b), "l"(c));
    return r;
}

__device__ __forceinline__ float wsum32(float v) {
#pragma unroll
    for (int o = 16; o > 0; o >>= 1) v += __shfl_xor_sync(0xffffffffu, v, o);
    return v;
}
__device__ __forceinline__ float bsum16(float v) {
#pragma unroll
    for (int o = 8; o > 0; o >>= 1) v += __shfl_xor_sync(0xffffffffu, v, o);
    return v;
}

// interior root of g x^2 - (g+2mu) x + mu = 0, cancellation-free:
//   t(a) = 2mu / (a + 2mu + sqrt(a^2+4mu^2)),  a = |g|;  x = g>=0 ? t : 1-t
// dx/dg = t'(a) = -t * rden * (1 + a/D)   (same for both signs)
__device__ __forceinline__ void xofg(float g, float& x, float& ndtda) {
    const float a   = fabsf(g);
    const float u   = fmaf(a, a, 4.0f * MU * MU);
    const float rD  = frsq(u);
    const float D   = u * rD;
    const float den = a + 2.0f * MU + D;
    const float rden = frcp(den);
    const float t   = (2.0f * MU) * rden;
    x = (g >= 0.0f) ? t : 1.0f - t;
    ndtda = (t * rden) * fmaf(a, rD, 1.0f);   // = -dx/dg  (positive)
}

// Pass A of the refine (identical math to the reference KKT refine), mu-scaled.
__device__ __forceinline__ void passA(
    const float4* __restrict__ sc, const float4* __restrict__ sw, int tid,
    const u64p* xP, u64p* qS, u64p* wiS, u64p* fiS,
    float lam, u64p one2, u64p none2, u64p n22,
    float& o1, float& o2, float& o3)
{
    const u64p lam2 = pack2(lam, lam);
    const u64p tmu2 = pack2(2.0f * MU, 2.0f * MU);
    const u64p nmu2 = pack2(-MU, -MU);
    u64p s1 = 0ull, s2 = 0ull, s3 = 0ull;
#pragma unroll
    for (int h = 0; h < 2; h++) {
        const float4 cf = sc[h * TPB + tid];
        const float4 wf = sw[h * TPB + tid];
#pragma unroll
        for (int j = 0; j < 2; j++) {
            const int idx = h * 2 + j;
            const u64p cv = j ? pack2(cf.z, cf.w) : pack2(cf.x, cf.y);
            const u64p wv = j ? pack2(wf.z, wf.w) : pack2(wf.x, wf.y);
            const u64p xv = xP[idx];
            const u64p omx = fma2(xv, none2, one2);     // 1-x
            const u64p p   = mul2(xv, omx);             // x(1-x)
            const u64p s   = fma2(p, n22, one2);        // 1-2p
            const u64p p2  = mul2(p, p);
            const u64p arg = mul2(p2, s);
            float a0, a1; unpack2(arg, a0, a1);
            const u64p r   = pack2(frcp(a0), frcp(a1)); // 1/(p^2 s)
            const u64p q   = mul2(r, mul2(p, s));       // 1/p
            const u64p iH  = mul2(r, mul2(p2, p2));     // mu/H
            const u64p t   = fma2(tmu2, xv, nmu2);      // mu(2x-1)
            const u64p f1  = fma2(t, q, fma2(lam2, wv, cv));
            const u64p wiH = mul2(wv, iH);
            qS[idx]  = q;
            wiS[idx] = wiH;
            fiS[idx] = mul2(f1, iH);
            s1 = fma2(xv,  wv, s1);    // sum x w
            s2 = fma2(wiH, f1, s2);    // mu * sum (w/H) F1
            s3 = fma2(wiH, wv, s3);    // mu * sum w^2/H
        }
    }
    float lo, hi;
    unpack2(s1, lo, hi); o1 = lo + hi;
    unpack2(s2, lo, hi); o2 = lo + hi;
    unpack2(s3, lo, hi); o3 = lo + hi;
}

__global__ void __launch_bounds__(TPB, 2)
ipm_kernel(const float* __restrict__ costs,
           const float* __restrict__ wglob,
           float* __restrict__ out)
{
    __shared__ float4 sc[2 * TPB];          // -costs row (16KB)
    __shared__ float4 sw[2 * TPB];          // weights    (16KB)
    __shared__ float sR[2][2][NWARP];       // [parity][s1|s2][warp]
    __shared__ float sA[NWARP], sB[NWARP], sC[NWARP];

    const int tid = threadIdx.x, lane = tid & 31, wid = tid >> 5;
    const float* crow = costs + (size_t)blockIdx.x * NITEMS;

    {
        const float4* cg = (const float4*)crow;
        const float4* wg = (const float4*)wglob;
        const float4 c0 = cg[tid], c1 = cg[TPB + tid];
        sc[tid]       = make_float4(-c0.x, -c0.y, -c0.z, -c0.w);
        sc[TPB + tid] = make_float4(-c1.x, -c1.y, -c1.z, -c1.w);
        sw[tid]       = wg[tid];
        sw[TPB + tid] = wg[TPB + tid];
    }
    __syncthreads();

    // ---- 1-D safeguarded Newton on lambda:  phi(lam) = sum w*x(lam) - CAP --
    float lam = 0.0f, lo = -30.0f, hi = 30.0f;

#pragma unroll 1
    for (int it = 0; it < MAXIT; ++it) {
        float s1 = 0.0f, s2 = 0.0f;     // s1 = sum w x, s2 = -phi'
#pragma unroll
        for (int h = 0; h < 2; h++) {
            const float4 cf = sc[h * TPB + tid];
            const float4 wf = sw[h * TPB + tid];
            float x, nd;
            xofg(fmaf(lam, wf.x, cf.x), x, nd);
            s1 = fmaf(wf.x, x, s1); s2 = fmaf(wf.x * wf.x, nd, s2);
            xofg(fmaf(lam, wf.y, cf.y), x, nd);
            s1 = fmaf(wf.y, x, s1); s2 = fmaf(wf.y * wf.y, nd, s2);
            xofg(fmaf(lam, wf.z, cf.z), x, nd);
            s1 = fmaf(wf.z, x, s1); s2 = fmaf(wf.z * wf.z, nd, s2);
            xofg(fmaf(lam, wf.w, cf.w), x, nd);
            s1 = fmaf(wf.w, x, s1); s2 = fmaf(wf.w * wf.w, nd, s2);
        }
        s1 = wsum32(s1); s2 = wsum32(s2);
        const int par = it & 1;
        if (lane == 0) { sR[par][0][wid] = s1; sR[par][1][wid] = s2; }
        __syncthreads();
        s1 = bsum16(sR[par][0][lane & 15]);     // identical in all threads
        s2 = bsum16(sR[par][1][lane & 15]);

        const float phi = s1 - CAP;
        if (phi > 0.0f) lo = lam; else hi = lam;   // phi monotone decreasing
        float ln = lam + phi * frcp(s2);           // Newton (phi' = -s2)
        if (!(ln > lo && ln < hi)) ln = 0.5f * (lo + hi);
        const float moved = ln - lam;
        lam = ln;
        if (fabsf(phi) < 5e-3f && fabsf(moved) < 1e-5f * (1.0f + fabsf(lam)))
            break;
    }

    // ---- build x(lam) elementwise (exact F1 = 0 by construction) -----------
    u64p xP[4], qS[4], wiS[4], fiS[4];
#pragma unroll
    for (int h = 0; h < 2; h++) {
        const float4 cf = sc[h * TPB + tid];
        const float4 wf = sw[h * TPB + tid];
        float x0, x1, x2, x3, nd;
        xofg(fmaf(lam, wf.x, cf.x), x0, nd);
        xofg(fmaf(lam, wf.y, cf.y), x1, nd);
        xofg(fmaf(lam, wf.z, cf.z), x2, nd);
        xofg(fmaf(lam, wf.w, cf.w), x3, nd);
        xP[h * 2]     = pack2(x0, x1);
        xP[h * 2 + 1] = pack2(x2, x3);
    }

    const u64p one2  = pack2(1.0f, 1.0f);
    const u64p none2 = pack2(-1.0f, -1.0f);
    const u64p n22   = pack2(-2.0f, -2.0f);

    // ---- KKT refine at mu = MU (same as reference): out = x + dx -----------
    {
        float s1, s2, s3;
        passA(sc, sw, tid, xP, qS, wiS, fiS, lam, one2, none2, n22, s1, s2, s3);
        s1 = wsum32(s1); s2 = wsum32(s2); s3 = wsum32(s3);
        if (lane == 0) { sA[wid] = s1; sB[wid] = s2; sC[wid] = s3; }
        __syncthreads();
        const float A  = bsum16(sA[lane & 15]);
        const float Bv = bsum16(sB[lane & 15]);
        const float Cv = bsum16(sC[lane & 15]);
        const float dlam = (MU * (A - CAP) - Bv) * frcp(Cv);   // scalar Schur

        const u64p dl2 = pack2(dlam, dlam);
        const float inv_mu = 1.0f / MU;
        const u64p ni2 = pack2(-inv_mu, -inv_mu);

        float4* orow = (float4*)(out + (size_t)blockIdx.x * NITEMS);
#pragma unroll
        for (int h = 0; h < 2; h++) {
            float4 o;
            {
                const int idx = h * 2;
                const u64p mm = fma2(dl2, wiS[idx], fiS[idx]);   // (F1+dlam w)*mu/H
                const u64p ov = fma2(ni2, mm, xP[idx]);          // x + dx
                unpack2(ov, o.x, o.y);
            }
            {
                const int idx = h * 2 + 1;
                const u64p mm = fma2(dl2, wiS[idx], fiS[idx]);
                const u64p ov = fma2(ni2, mm, xP[idx]);
                unpack2(ov, o.z, o.w);
            }
            orow[h * TPB + tid] = o;
        }
    }
}

extern "C" void kernel_launch(void* const* d_in, const int* in_sizes, int n_in,
                              void* d_out, int out_size)
{
    const float* costs = (const float*)d_in[0];
    const float* wv    = (const float*)d_in[1];
    int costs_elems = in_sizes[0];
    if (n_in >= 2 && in_sizes[0] == NITEMS && in_sizes[1] > NITEMS) {
        costs = (const float*)d_in[1];
        wv    = (const float*)d_in[0];
        costs_elems = in_sizes[1];
    }
    const int B = costs_elems / NITEMS;
    ipm_kernel<<<B, TPB>>>(costs, wv, (float*)d_out);
}